// round 6
// baseline (speedup 1.0000x reference)
#include <cuda_runtime.h>
#include <cuda_bf16.h>
#include <math_constants.h>

// Problem shape (fixed by dataset)
#define NN 100000
#define NE 1600000
#define INF_ 128
#define OUTF 64
#define SCAN_NB 391          // ceil(NN/256)

// ---------------- device scratch (static: no runtime allocation) -------------
// NOTE lifecycle: g_deg is zero at every kernel_launch entry — zero-initialized
// at load, and re-zeroed by k_aggregate at the end of every executed call
// (graph capture does not execute, so the invariant holds across replays).
__device__ float g_ft[(size_t)NN * OUTF];       // projected features  [N,64]
__device__ int   g_deg[NN];                     // in-degree histogram
__device__ int   g_offs[NN + 1];                // CSR offsets by dst
__device__ int   g_cursor[NN];                  // scatter cursors
__device__ int   g_csr_src[NE];                 // src node per CSR slot
__device__ unsigned long long g_state[SCAN_NB]; // lookback: (status<<32)|sum

__device__ __forceinline__ int clampidx(int v) {
    unsigned u = (unsigned)v;
    return (u < (unsigned)NN) ? v : 0;
}

// packed f32x2 helpers (Blackwell: FFMA2 only reachable from PTX)
__device__ __forceinline__ unsigned long long pack2(float lo, float hi) {
    unsigned long long r;
    asm("mov.b64 %0, {%1, %2};" : "=l"(r) : "f"(lo), "f"(hi));
    return r;
}
__device__ __forceinline__ void unpack2(unsigned long long v, float& lo, float& hi) {
    asm("mov.b64 {%0, %1}, %2;" : "=f"(lo), "=f"(hi) : "l"(v));
}
__device__ __forceinline__ void fma2(unsigned long long& d,
                                     unsigned long long a, unsigned long long b) {
    asm("fma.rn.f32x2 %0, %1, %2, %0;" : "+l"(d) : "l"(a), "l"(b));
}

// ---------------- K1: in-degree histogram + scan-state reset -----------------
__global__ __launch_bounds__(256) void k_deg(const int* __restrict__ dst) {
    int t = blockIdx.x * blockDim.x + threadIdx.x;
    if (t < SCAN_NB) g_state[t] = 0ull;       // consumed by k_scan (next launch)
    if (t >= NE / 4) return;
    int4 d4 = ((const int4*)dst)[t];
    atomicAdd(&g_deg[clampidx(d4.x)], 1);
    atomicAdd(&g_deg[clampidx(d4.y)], 1);
    atomicAdd(&g_deg[clampidx(d4.z)], 1);
    atomicAdd(&g_deg[clampidx(d4.w)], 1);
}

// ---------------- K2: single-pass decoupled-lookback exclusive scan ----------
__global__ __launch_bounds__(256) void k_scan() {
    __shared__ int wsum[8];
    __shared__ int bprefix;
    int b = blockIdx.x;
    int tid = threadIdx.x;
    int lane = tid & 31;
    int wid = tid >> 5;
    int i = b * 256 + tid;

    int v = (i < NN) ? g_deg[i] : 0;
    int x = v;
#pragma unroll
    for (int o = 1; o < 32; o <<= 1) {
        int t = __shfl_up_sync(0xffffffffu, x, o);
        if (lane >= o) x += t;
    }
    if (lane == 31) wsum[wid] = x;
    __syncthreads();
    if (wid == 0) {
        int y = (lane < 8) ? wsum[lane] : 0;
#pragma unroll
        for (int o = 1; o < 8; o <<= 1) {
            int t = __shfl_up_sync(0xffffffffu, y, o);
            if (lane >= o) y += t;
        }
        if (lane < 8) wsum[lane] = y;
    }
    __syncthreads();
    int incl = x + ((wid > 0) ? wsum[wid - 1] : 0);
    int btotal = wsum[7];

    if (tid == 0) {
        if (b == 0) {
            atomicExch(&g_state[0], (2ull << 32) | (unsigned)btotal);
            bprefix = 0;
        } else {
            atomicExch(&g_state[b], (1ull << 32) | (unsigned)btotal);
            long long ex = 0;
            int pred = b - 1;
            while (true) {
                unsigned long long s =
                    *((volatile unsigned long long*)&g_state[pred]);
                unsigned st = (unsigned)(s >> 32);
                if (st == 0) continue;
                ex += (unsigned)s;
                if (st == 2) break;
                pred--;
            }
            atomicExch(&g_state[b], (2ull << 32) | (unsigned)(ex + btotal));
            bprefix = (int)ex;
        }
    }
    __syncthreads();

    if (i < NN) {
        int o = bprefix + incl - v;
        g_offs[i] = o;
        g_cursor[i] = o;
    }
    if (i == 0) g_offs[NN] = NE;
}

// ---------------- K3: scatter into CSR (4 atomics batched -> 4 stores) -------
__global__ __launch_bounds__(256) void k_scatter(const int* __restrict__ src,
                                                 const int* __restrict__ dst) {
    int t = blockIdx.x * blockDim.x + threadIdx.x;
    if (t >= NE / 4) return;
    int4 s4 = ((const int4*)src)[t];
    int4 d4 = ((const int4*)dst)[t];
    // issue all atomics first (4 independent ATOMGs in flight), then stores
    int p0 = atomicAdd(&g_cursor[clampidx(d4.x)], 1);
    int p1 = atomicAdd(&g_cursor[clampidx(d4.y)], 1);
    int p2 = atomicAdd(&g_cursor[clampidx(d4.z)], 1);
    int p3 = atomicAdd(&g_cursor[clampidx(d4.w)], 1);
    g_csr_src[p0] = clampidx(s4.x);
    g_csr_src[p1] = clampidx(s4.y);
    g_csr_src[p2] = clampidx(s4.z);
    g_csr_src[p3] = clampidx(s4.w);
}

// ---------------- K4: ft = feat @ W  (64x64 tile, f32x2 FFMA2) ---------------
__global__ __launch_bounds__(256) void k_gemm(const float* __restrict__ feat,
                                              const float* __restrict__ Wm) {
    __shared__ float wsm[INF_ * OUTF];   // 32 KB
    int tid = threadIdx.x;

    for (int i = tid; i < (INF_ * OUTF) / 4; i += 256)
        ((float4*)wsm)[i] = ((const float4*)Wm)[i];
    __syncthreads();

    int row0 = blockIdx.x * 64 + (tid >> 4) * 4;   // 4 rows
    int c0 = (tid & 15) * 4;                       // 4 cols

    int r[4];
#pragma unroll
    for (int i = 0; i < 4; i++) r[i] = (row0 + i < NN) ? row0 + i : 0;

    unsigned long long acc[4][2];
#pragma unroll
    for (int i = 0; i < 4; i++) { acc[i][0] = 0ull; acc[i][1] = 0ull; }

#pragma unroll 2
    for (int kk = 0; kk < INF_ / 4; kk++) {
        float4 fr[4];
#pragma unroll
        for (int i = 0; i < 4; i++)
            fr[i] = ((const float4*)(feat + (size_t)r[i] * INF_))[kk];
#pragma unroll
        for (int j = 0; j < 4; j++) {
            float4 w4 = *(const float4*)(wsm + (kk * 4 + j) * OUTF + c0);
            unsigned long long bxy = pack2(w4.x, w4.y);
            unsigned long long bzw = pack2(w4.z, w4.w);
#pragma unroll
            for (int i = 0; i < 4; i++) {
                float f = (j == 0) ? fr[i].x : (j == 1) ? fr[i].y
                         : (j == 2) ? fr[i].z : fr[i].w;
                unsigned long long a2 = pack2(f, f);
                fma2(acc[i][0], a2, bxy);
                fma2(acc[i][1], a2, bzw);
            }
        }
    }

#pragma unroll
    for (int i = 0; i < 4; i++) {
        int row = row0 + i;
        if (row < NN) {
            float4 o;
            unpack2(acc[i][0], o.x, o.y);
            unpack2(acc[i][1], o.z, o.w);
            *(float4*)(g_ft + (size_t)row * OUTF + c0) = o;
        }
    }
}

// ---------------- K5: fused score + ONLINE softmax + aggregation -------------
// One warp per node. Each 16-lane HALF loads a full 256B feature row per
// LDG.128 (lane hl owns dims 4hl..4hl+3) and processes a disjoint edge
// subset (stride 2) with its own online (m,s,acc). Halves merged at the end.
__global__ __launch_bounds__(256) void k_aggregate(float* __restrict__ out) {
    int w = threadIdx.x >> 5;
    int lane = threadIdx.x & 31;
    int node = blockIdx.x * 8 + w;
    if (node >= NN) return;

    int lo = g_offs[node];
    int hi = g_offs[node + 1];
    if (lane == 0) g_deg[node] = 0;          // reset for next replay

    int h = lane >> 4;                       // half id (0/1)
    int hl = lane & 15;                      // lane within half
    unsigned hmask = 0xFFFFu << (h * 16);

    if (lo == hi) {                          // zero in-degree
        if (h == 0)
            *(float4*)(out + (size_t)node * OUTF + hl * 4) =
                make_float4(0.f, 0.f, 0.f, 0.f);
        return;
    }

    float4 df = *(const float4*)(g_ft + (size_t)node * OUTF + hl * 4);

    float m = -CUDART_INF_F;
    float s = 0.f;
    float4 acc = make_float4(0.f, 0.f, 0.f, 0.f);

    int j = lo + h;
    // 2 edges per half per iteration (j, j+2)
    for (; j + 2 < hi; j += 4) {
        int s0 = g_csr_src[j];
        int s1 = g_csr_src[j + 2];
        float4 f0 = *(const float4*)(g_ft + (size_t)s0 * OUTF + hl * 4);
        float4 f1 = *(const float4*)(g_ft + (size_t)s1 * OUTF + hl * 4);
        float p0 = f0.x * df.x + f0.y * df.y + f0.z * df.z + f0.w * df.w;
        float p1 = f1.x * df.x + f1.y * df.y + f1.z * df.z + f1.w * df.w;
#pragma unroll
        for (int o = 8; o; o >>= 1) {
            p0 += __shfl_xor_sync(hmask, p0, o);
            p1 += __shfl_xor_sync(hmask, p1, o);
        }
        float mn = fmaxf(p0, p1);
        if (mn > m) {                        // uniform within half
            float rsc = __expf(m - mn);      // first hit: exp(-inf)=0
            s *= rsc;
            acc.x *= rsc; acc.y *= rsc; acc.z *= rsc; acc.w *= rsc;
            m = mn;
        }
        float w0 = __expf(p0 - m);
        float w1 = __expf(p1 - m);
        s += w0 + w1;
        acc.x += w0 * f0.x + w1 * f1.x;
        acc.y += w0 * f0.y + w1 * f1.y;
        acc.z += w0 * f0.z + w1 * f1.z;
        acc.w += w0 * f0.w + w1 * f1.w;
    }
    // remainder for this half (0 or 1 edge)
    for (; j < hi; j += 2) {
        int s0 = g_csr_src[j];
        float4 f0 = *(const float4*)(g_ft + (size_t)s0 * OUTF + hl * 4);
        float p0 = f0.x * df.x + f0.y * df.y + f0.z * df.z + f0.w * df.w;
#pragma unroll
        for (int o = 8; o; o >>= 1) p0 += __shfl_xor_sync(hmask, p0, o);
        if (p0 > m) {
            float rsc = __expf(m - p0);
            s *= rsc;
            acc.x *= rsc; acc.y *= rsc; acc.z *= rsc; acc.w *= rsc;
            m = p0;
        }
        float w0 = __expf(p0 - m);
        s += w0;
        acc.x += w0 * f0.x; acc.y += w0 * f0.y;
        acc.z += w0 * f0.z; acc.w += w0 * f0.w;
    }

    // merge the two halves (flash-style). Empty half: m=-inf -> weight 0.
    __syncwarp();
    float pm = __shfl_xor_sync(0xffffffffu, m, 16);
    float ps = __shfl_xor_sync(0xffffffffu, s, 16);
    float px = __shfl_xor_sync(0xffffffffu, acc.x, 16);
    float py = __shfl_xor_sync(0xffffffffu, acc.y, 16);
    float pz = __shfl_xor_sync(0xffffffffu, acc.z, 16);
    float pw = __shfl_xor_sync(0xffffffffu, acc.w, 16);
    float M = fmaxf(m, pm);
    float r1 = __expf(m - M);                // -inf-M -> 0 (only if half empty)
    float r2 = __expf(pm - M);
    float S = s * r1 + ps * r2;
    float inv = 1.f / S;
    float4 o;
    o.x = (acc.x * r1 + px * r2) * inv;
    o.y = (acc.y * r1 + py * r2) * inv;
    o.z = (acc.z * r1 + pz * r2) * inv;
    o.w = (acc.w * r1 + pw * r2) * inv;
    if (h == 0)
        *(float4*)(out + (size_t)node * OUTF + hl * 4) = o;
}

// ---------------- launch ------------------------------------------------------
extern "C" void kernel_launch(void* const* d_in, const int* in_sizes, int n_in,
                              void* d_out, int out_size) {
    const float* feat = (const float*)d_in[0];
    const float* Wm   = (const float*)d_in[1];
    const int*   src  = (const int*)d_in[2];
    const int*   dst  = (const int*)d_in[3];
    float* out = (float*)d_out;

    int nbE4 = (NE / 4 + 255) / 256;         // 1563
    int nbG  = (NN + 63) / 64;               // 1563
    int nbA  = (NN + 7) / 8;                 // 12500

    k_deg<<<nbE4, 256>>>(dst);
    k_scan<<<SCAN_NB, 256>>>();
    k_scatter<<<nbE4, 256>>>(src, dst);
    k_gemm<<<nbG, 256>>>(feat, Wm);
    k_aggregate<<<nbA, 256>>>(out);
}